// round 1
// baseline (speedup 1.0000x reference)
#include <cuda_runtime.h>
#include <cuda_bf16.h>

#define NSPEC 300
#define NM    9
#define NL    5
#define KTAPS 16
#define RPB   8                    // rows (=warps) per block
#define THREADS (RPB * 32)
#define NCH   10                   // ceil(300/32)
#define STR   304                  // stride for plain per-row arrays
#define RSTR  336                  // residual-with-halo: 16 + 300 + 16 = 332 -> 336
#define ROW_FLOATS (6 * STR + RSTR)

// Precomputed per-layer factors (small)
__device__ float d_taps[NL][KTAPS + 1];
__device__ float d_W[NL][NSPEC * NM];      // W[j*9+m] = (M^-1 A^T)[j][m]
__device__ float d_S[NL][NM * NM];
__device__ float d_Sinv[NL][NM * NM];

// ---------------------------------------------------------------------------
// Precompute: per layer, solve cyclic-tridiagonal systems (Thomas + Sherman-
// Morrison) for M^-1 e0 (taps), M^-1 A^T (W), then S = I + A M^-1 A^T and S^-1.
// All big temporaries live in dynamic shared memory.
// smem layout (floats): im[5*300] | q[5*300] | denom[8] | y[50*300]
// ---------------------------------------------------------------------------
#define PRE_SMEM_FLOATS (5 * NSPEC * 2 + 8 + 50 * NSPEC)

__global__ void precompute_kernel(const float* __restrict__ A,
                                  const float* __restrict__ gamma_tv,
                                  const float* __restrict__ alpha) {
    extern __shared__ float psm[];
    float* im    = psm;                       // [5][300] 1/m_i forward factors
    float* qv    = im + NL * NSPEC;           // [5][300] q = T^-1 u
    float* denom = qv + NL * NSPEC;           // [5] 1/(1 + v.q)
    float* ys    = denom + 8;                 // [50][300]

    int t = threadIdx.x;

    // Stage 1: per-layer forward factors + q vector (5 threads, serial Thomas)
    if (t < NL) {
        float g  = gamma_tv[t];
        float al = alpha[t];
        float D0 = al + 2.f * g;
        float off = -g;
        float b0v = 2.f * D0;                 // T[0][0] with gamma = -D0
        float bnv = D0 + (g * g) / D0;        // T[n-1][n-1]
        float* imL = im + t * NSPEC;
        float* qL  = qv + t * NSPEC;
        float prev_cp = 0.f, prev_q = 0.f;
        for (int i = 0; i < NSPEC; i++) {
            float di = (i == 0) ? b0v : ((i == NSPEC - 1) ? bnv : D0);
            float m  = di - off * prev_cp;
            float imi = 1.f / m;
            imL[i] = imi;
            float ui = (i == 0) ? -D0 : ((i == NSPEC - 1) ? -g : 0.f);
            float qi = (ui - off * prev_q) * imi;
            qL[i] = qi;
            prev_cp = off * imi;
            prev_q  = qi;
        }
        for (int i = NSPEC - 2; i >= 0; i--)
            qL[i] -= off * imL[i] * qL[i + 1];
        float cg = g / D0;                    // c_up/gamma = (-g)/(-D0)
        denom[t] = 1.f / (1.f + qL[0] + cg * qL[NSPEC - 1]);
    }
    __syncthreads();

    // Stage 2: 50 solves (5 layers x {e0, 9 rows of A})
    if (t < NL * 10) {
        int L = t / 10, rhs = t % 10;
        float g  = gamma_tv[L];
        float al = alpha[L];
        float D0 = al + 2.f * g;
        float off = -g;
        float* imL = im + L * NSPEC;
        float* qL  = qv + L * NSPEC;
        float* y   = ys + t * NSPEC;
        const float* Arow = (rhs > 0) ? (A + (rhs - 1) * NSPEC) : nullptr;
        float prev = 0.f;
        for (int i = 0; i < NSPEC; i++) {
            float ri = (rhs == 0) ? ((i == 0) ? 1.f : 0.f) : Arow[i];
            float yi = (ri - off * prev) * imL[i];
            y[i] = yi;
            prev = yi;
        }
        for (int i = NSPEC - 2; i >= 0; i--)
            y[i] -= off * imL[i] * y[i + 1];
        float cg = g / D0;
        float fact = (y[0] + cg * y[NSPEC - 1]) * denom[L];
        if (rhs == 0) {
            for (int k = 0; k <= KTAPS; k++)
                d_taps[L][k] = y[k] - fact * qL[k];
        } else {
            int m = rhs - 1;
            for (int j = 0; j < NSPEC; j++)
                d_W[L][j * NM + m] = y[j] - fact * qL[j];
        }
    }
    __syncthreads();

    // Stage 3: S = I9 + A * W (405 independent entries)
    for (int idx = t; idx < NL * NM * NM; idx += blockDim.x) {
        int L = idx / (NM * NM);
        int pq = idx % (NM * NM);
        int p = pq / NM, q2 = pq % NM;
        float s = (p == q2) ? 1.f : 0.f;
        const float* Ap = A + p * NSPEC;
        for (int j = 0; j < NSPEC; j++)
            s = fmaf(Ap[j], d_W[L][j * NM + q2], s);
        d_S[L][pq] = s;
    }
    __syncthreads();

    // Stage 4: invert 9x9 per layer (Gauss-Jordan w/ partial pivoting)
    if (t < NL) {
        float Mi[NM][2 * NM];
        for (int i = 0; i < NM; i++)
            for (int j = 0; j < NM; j++) {
                Mi[i][j] = d_S[t][i * NM + j];
                Mi[i][NM + j] = (i == j) ? 1.f : 0.f;
            }
        for (int col = 0; col < NM; col++) {
            int piv = col;
            float best = fabsf(Mi[col][col]);
            for (int r = col + 1; r < NM; r++) {
                float v = fabsf(Mi[r][col]);
                if (v > best) { best = v; piv = r; }
            }
            if (piv != col)
                for (int j = 0; j < 2 * NM; j++) {
                    float tmp = Mi[col][j]; Mi[col][j] = Mi[piv][j]; Mi[piv][j] = tmp;
                }
            float ip = 1.f / Mi[col][col];
            for (int j = 0; j < 2 * NM; j++) Mi[col][j] *= ip;
            for (int r = 0; r < NM; r++) {
                if (r == col) continue;
                float f = Mi[r][col];
                for (int j = 0; j < 2 * NM; j++) Mi[r][j] -= f * Mi[col][j];
            }
        }
        for (int i = 0; i < NM; i++)
            for (int j = 0; j < NM; j++)
                d_Sinv[t][i * NM + j] = Mi[i][NM + j];
    }
}

// ---------------------------------------------------------------------------
// Main fused kernel: one warp per row, all 5 layers, state in shared memory.
// smem layout (floats): A_s[9*300] | W_s[300*9] | Sinv_s[84] | rows[RPB][ROW_FLOATS]
// ---------------------------------------------------------------------------
#define MAIN_SMEM_FLOATS (NM * NSPEC + NM * NSPEC + 84 + RPB * ROW_FLOATS)

__global__ void __launch_bounds__(THREADS)
ladmm_kernel(const float* __restrict__ b,
             const float* __restrict__ A,
             const float* __restrict__ gamma_tv,
             const float* __restrict__ lambda_tv,
             const float* __restrict__ alpha,
             float* __restrict__ out) {
    extern __shared__ float sm[];
    float* A_s    = sm;
    float* W_s    = A_s + NM * NSPEC;
    float* Sinv_s = W_s + NM * NSPEC;
    float* rows   = Sinv_s + 84;

    int tid  = threadIdx.x;
    int warp = tid >> 5;
    int lane = tid & 31;
    int row  = blockIdx.x * RPB + warp;

    float* xs  = rows + warp * ROW_FLOATS;
    float* eta = xs + STR;
    float* tau = eta + STR;
    float* us  = tau + STR;
    float* ws  = us + STR;
    float* bAs = ws + STR;
    float* rh  = bAs + STR;                 // residual with halo; center at rh+KTAPS

    // Load A into smem
    for (int i = tid; i < NM * NSPEC; i += THREADS) A_s[i] = A[i];
    __syncthreads();

    // Load b row into registers; init state; precompute bA row
    float brow[NM];
    const float* bp = b + (size_t)row * NM;
#pragma unroll
    for (int m = 0; m < NM; m++) brow[m] = bp[m];

#pragma unroll
    for (int c = 0; c < NCH; c++) {
        int j = c * 32 + lane;
        if (j < NSPEC) {
            xs[j] = 1.f; eta[j] = 0.f; tau[j] = 0.f;
            float ba = 0.f;
#pragma unroll
            for (int m = 0; m < NM; m++) ba = fmaf(brow[m], A_s[m * NSPEC + j], ba);
            bAs[j] = ba;
        }
    }
    __syncwarp();

    for (int L = 0; L < NL; L++) {
        float g   = gamma_tv[L];
        float lam = lambda_tv[L];
        float al  = alpha[L];
        float ig  = 1.f / g;
        float ial = 1.f / al;
        float thr = lam * ig;

        // Swap in this layer's W and Sinv (block-cooperative)
        __syncthreads();
        for (int i = tid; i < NM * NSPEC; i += THREADS) W_s[i] = d_W[L][i];
        for (int i = tid; i < NM * NM; i += THREADS)    Sinv_s[i] = d_Sinv[L][i];
        __syncthreads();

        float taps[KTAPS + 1];
#pragma unroll
        for (int k = 0; k <= KTAPS; k++) taps[k] = d_taps[L][k];

        // Elementwise: u_tv, w, residual (into halo array)
#pragma unroll
        for (int c = 0; c < NCH; c++) {
            int j = c * 32 + lane;
            if (j < NSPEC) {
                int jm = (j == 0) ? NSPEC - 1 : j - 1;
                float xj = xs[j];
                float dx = xs[jm] - xj;
                float ej = eta[j];
                float tj = tau[j];
                float v  = fmaf(ej, ig, dx);
                float ua = fmaxf(fabsf(v) - thr, 0.f);
                float u  = (v >= 0.f) ? ua : -ua;
                us[j] = u;
                float wv = fmaxf(fmaf(tj, ial, xj), 0.f);
                ws[j] = wv;
                rh[KTAPS + j] = bAs[j] + al * wv - tj + g * u - ej;
            }
        }
        __syncwarp();
        // Halo fill: 2K = 32 entries, one per lane
        if (lane < KTAPS) {
            rh[lane] = rh[NSPEC + lane];                    // left: r[300-16+lane]
        } else {
            rh[NSPEC + lane] = rh[lane];                    // right: r[lane-16]
        }
        __syncwarp();

        // z = M^-1 r via truncated symmetric circulant conv; write z into xs
#pragma unroll
        for (int c = 0; c < NCH; c++) {
            int j = c * 32 + lane;
            if (j < NSPEC) {
                const float* p = rh + KTAPS + j;
                float acc = taps[0] * p[0];
#pragma unroll
                for (int k = 1; k <= KTAPS; k++)
                    acc = fmaf(taps[k], p[k] + p[-k], acc);
                xs[j] = acc;
            }
        }
        __syncwarp();

        // c = A z (warp reduction)
        float cp[NM];
#pragma unroll
        for (int m = 0; m < NM; m++) cp[m] = 0.f;
#pragma unroll
        for (int c = 0; c < NCH; c++) {
            int j = c * 32 + lane;
            if (j < NSPEC) {
                float zj = xs[j];
#pragma unroll
                for (int m = 0; m < NM; m++)
                    cp[m] = fmaf(A_s[m * NSPEC + j], zj, cp[m]);
            }
        }
#pragma unroll
        for (int m = 0; m < NM; m++) {
#pragma unroll
            for (int o = 16; o > 0; o >>= 1)
                cp[m] += __shfl_xor_sync(0xffffffffu, cp[m], o);
        }

        // d = Sinv * c (lane-redundant, tiny)
        float dv[NM];
#pragma unroll
        for (int p2 = 0; p2 < NM; p2++) {
            float s = 0.f;
#pragma unroll
            for (int q2 = 0; q2 < NM; q2++)
                s = fmaf(Sinv_s[p2 * NM + q2], cp[q2], s);
            dv[p2] = s;
        }

        // x = z - W d
#pragma unroll
        for (int c = 0; c < NCH; c++) {
            int j = c * 32 + lane;
            if (j < NSPEC) {
                float s = xs[j];
#pragma unroll
                for (int m = 0; m < NM; m++)
                    s = fmaf(-W_s[j * NM + m], dv[m], s);
                xs[j] = s;
            }
        }
        __syncwarp();

        // Dual updates
#pragma unroll
        for (int c = 0; c < NCH; c++) {
            int j = c * 32 + lane;
            if (j < NSPEC) {
                int jm = (j == 0) ? NSPEC - 1 : j - 1;
                float xn  = xs[j];
                float dxn = xs[jm] - xn;
                eta[j] = fmaf(g, dxn - us[j], eta[j]);
                tau[j] = fmaf(al, xn - ws[j], tau[j]);
            }
        }
        __syncwarp();
    }

    // Write final x
#pragma unroll
    for (int c = 0; c < NCH; c++) {
        int j = c * 32 + lane;
        if (j < NSPEC) out[(size_t)row * NSPEC + j] = xs[j];
    }
}

// ---------------------------------------------------------------------------
extern "C" void kernel_launch(void* const* d_in, const int* in_sizes, int n_in,
                              void* d_out, int out_size) {
    const float* b      = (const float*)d_in[0];
    // d_in[1] = target (only defines shape/init in reference; unused numerically)
    const float* A      = (const float*)d_in[2];
    const float* gamma  = (const float*)d_in[3];
    const float* lam    = (const float*)d_in[4];
    const float* alpha  = (const float*)d_in[5];
    float* out = (float*)d_out;

    int rows = in_sizes[0] / NM;           // 131072

    size_t pre_smem  = PRE_SMEM_FLOATS * sizeof(float);
    size_t main_smem = MAIN_SMEM_FLOATS * sizeof(float);
    cudaFuncSetAttribute(precompute_kernel,
                         cudaFuncAttributeMaxDynamicSharedMemorySize, (int)pre_smem);
    cudaFuncSetAttribute(ladmm_kernel,
                         cudaFuncAttributeMaxDynamicSharedMemorySize, (int)main_smem);

    precompute_kernel<<<1, 512, pre_smem>>>(A, gamma, alpha);
    ladmm_kernel<<<rows / RPB, THREADS, main_smem>>>(b, A, gamma, lam, alpha, out);
}

// round 2
// speedup vs baseline: 1.6180x; 1.6180x over previous
#include <cuda_runtime.h>
#include <cuda_bf16.h>

#define NSPEC 300
#define NM    9
#define NL    5
#define KTAPS 16            // taps computed in precompute
#define KT    12            // taps used in main conv
#define RPB   8             // rows (=warps) per block
#define THREADS (RPB * 32)
#define PSTR  332           // padded stride: 300 + 30 pads + slack (11 floats per lane-run)

// Precomputed per-layer factors
__device__ float d_taps[NL][KTAPS + 1];
__device__ float d_W[NL][NSPEC * NM];      // W[j*9+m] = (M^-1 A^T)[j][m]
__device__ float d_S[NL][NM * NM];
__device__ float d_Sinv[NL][NM * NM];
__device__ float d_V[NL][NM * NSPEC];      // V = W * Sinv, stored [m][j]

// ---------------------------------------------------------------------------
// Precompute kernel (1 block): Thomas+Sherman-Morrison solves for taps and W,
// S = I + A W, Sinv, V = W Sinv.
// ---------------------------------------------------------------------------
#define PRE_SMEM_FLOATS (5 * NSPEC * 2 + 8 + 50 * NSPEC)

__global__ void precompute_kernel(const float* __restrict__ A,
                                  const float* __restrict__ gamma_tv,
                                  const float* __restrict__ alpha) {
    extern __shared__ float psm[];
    float* im    = psm;                       // [5][300]
    float* qv    = im + NL * NSPEC;           // [5][300]
    float* denom = qv + NL * NSPEC;           // [5]
    float* ys    = denom + 8;                 // [50][300]

    int t = threadIdx.x;

    // Stage 1: per-layer Thomas forward factors + q (Sherman-Morrison vector)
    if (t < NL) {
        float g  = gamma_tv[t];
        float al = alpha[t];
        float D0 = al + 2.f * g;
        float off = -g;
        float b0v = 2.f * D0;
        float bnv = D0 + (g * g) / D0;
        float* imL = im + t * NSPEC;
        float* qL  = qv + t * NSPEC;
        float prev_cp = 0.f, prev_q = 0.f;
        for (int i = 0; i < NSPEC; i++) {
            float di = (i == 0) ? b0v : ((i == NSPEC - 1) ? bnv : D0);
            float m  = di - off * prev_cp;
            float imi = 1.f / m;
            imL[i] = imi;
            float ui = (i == 0) ? -D0 : ((i == NSPEC - 1) ? -g : 0.f);
            float qi = (ui - off * prev_q) * imi;
            qL[i] = qi;
            prev_cp = off * imi;
            prev_q  = qi;
        }
        for (int i = NSPEC - 2; i >= 0; i--)
            qL[i] -= off * imL[i] * qL[i + 1];
        float cg = g / D0;
        denom[t] = 1.f / (1.f + qL[0] + cg * qL[NSPEC - 1]);
    }
    __syncthreads();

    // Stage 2: 50 solves (5 layers x {e0, 9 rows of A})
    if (t < NL * 10) {
        int L = t / 10, rhs = t % 10;
        float g  = gamma_tv[L];
        float al = alpha[L];
        float D0 = al + 2.f * g;
        float off = -g;
        float* imL = im + L * NSPEC;
        float* qL  = qv + L * NSPEC;
        float* y   = ys + t * NSPEC;
        const float* Arow = (rhs > 0) ? (A + (rhs - 1) * NSPEC) : nullptr;
        float prev = 0.f;
        for (int i = 0; i < NSPEC; i++) {
            float ri = (rhs == 0) ? ((i == 0) ? 1.f : 0.f) : Arow[i];
            float yi = (ri - off * prev) * imL[i];
            y[i] = yi;
            prev = yi;
        }
        for (int i = NSPEC - 2; i >= 0; i--)
            y[i] -= off * imL[i] * y[i + 1];
        float cg = g / D0;
        float fact = (y[0] + cg * y[NSPEC - 1]) * denom[L];
        if (rhs == 0) {
            for (int k = 0; k <= KTAPS; k++)
                d_taps[L][k] = y[k] - fact * qv[L * NSPEC + k];
        } else {
            int m = rhs - 1;
            for (int j = 0; j < NSPEC; j++)
                d_W[L][j * NM + m] = y[j] - fact * qv[L * NSPEC + j];
        }
    }
    __syncthreads();

    // Stage 3: S = I9 + A * W
    for (int idx = t; idx < NL * NM * NM; idx += blockDim.x) {
        int L = idx / (NM * NM);
        int pq = idx % (NM * NM);
        int p = pq / NM, q2 = pq % NM;
        float s = (p == q2) ? 1.f : 0.f;
        const float* Ap = A + p * NSPEC;
        for (int j = 0; j < NSPEC; j++)
            s = fmaf(Ap[j], d_W[L][j * NM + q2], s);
        d_S[L][pq] = s;
    }
    __syncthreads();

    // Stage 4: invert 9x9 per layer (Gauss-Jordan, partial pivoting)
    if (t < NL) {
        float Mi[NM][2 * NM];
        for (int i = 0; i < NM; i++)
            for (int j = 0; j < NM; j++) {
                Mi[i][j] = d_S[t][i * NM + j];
                Mi[i][NM + j] = (i == j) ? 1.f : 0.f;
            }
        for (int col = 0; col < NM; col++) {
            int piv = col;
            float best = fabsf(Mi[col][col]);
            for (int r = col + 1; r < NM; r++) {
                float v = fabsf(Mi[r][col]);
                if (v > best) { best = v; piv = r; }
            }
            if (piv != col)
                for (int j = 0; j < 2 * NM; j++) {
                    float tmp = Mi[col][j]; Mi[col][j] = Mi[piv][j]; Mi[piv][j] = tmp;
                }
            float ip = 1.f / Mi[col][col];
            for (int j = 0; j < 2 * NM; j++) Mi[col][j] *= ip;
            for (int r = 0; r < NM; r++) {
                if (r == col) continue;
                float f = Mi[r][col];
                for (int j = 0; j < 2 * NM; j++) Mi[r][j] -= f * Mi[col][j];
            }
        }
        for (int i = 0; i < NM; i++)
            for (int j = 0; j < NM; j++)
                d_Sinv[t][i * NM + j] = Mi[i][NM + j];
    }
    __syncthreads();

    // Stage 5: V = W * Sinv, stored as [L][m][j]
    for (int idx = t; idx < NL * NM * NSPEC; idx += blockDim.x) {
        int L = idx / (NM * NSPEC);
        int mj = idx % (NM * NSPEC);
        int m = mj / NSPEC, j = mj % NSPEC;
        float s = 0.f;
        for (int q = 0; q < NM; q++)
            s = fmaf(d_W[L][j * NM + q], d_Sinv[L][q * NM + m], s);
        d_V[L][m * NSPEC + j] = s;
    }
}

// ---------------------------------------------------------------------------
// Main kernel: one warp per row, 30 active lanes x 10 contiguous elements,
// fully register-resident state; smem only for A (padded) and V (padded).
// smem: A_s[9*332] | V_s[45*332]   (pad: element j stored at j + j/10,
//  i.e. lane-run address = m*332 + lane*11 + i -> odd lane-stride, 0 conflicts)
// ---------------------------------------------------------------------------
#define MAIN_SMEM_FLOATS (NM * PSTR + NL * NM * PSTR)

__global__ void __launch_bounds__(THREADS, 2)
ladmm_kernel(const float* __restrict__ b,
             const float* __restrict__ A,
             const float* __restrict__ gamma_tv,
             const float* __restrict__ lambda_tv,
             const float* __restrict__ alpha,
             float* __restrict__ out) {
    extern __shared__ float sm[];
    float* A_s = sm;                          // [9][332]
    float* V_s = A_s + NM * PSTR;             // [45][332]

    int tid  = threadIdx.x;
    int warp = tid >> 5;
    int lane = tid & 31;
    int row  = blockIdx.x * RPB + warp;

    // Cooperative load of A and V into padded smem
    for (int idx = tid; idx < NM * NSPEC; idx += THREADS) {
        int m = idx / NSPEC, j = idx % NSPEC;
        A_s[m * PSTR + j + j / 10] = A[idx];
    }
    for (int idx = tid; idx < NL * NM * NSPEC; idx += THREADS) {
        int r = idx / NSPEC, j = idx % NSPEC;   // r = L*9+m
        V_s[r * PSTR + j + j / 10] = (&d_V[0][0])[idx];
    }
    __syncthreads();

    int ml  = (lane < 30) ? lane : 29;        // clamped for smem addressing
    int base = ml * 11;
    int lm1 = (lane == 0) ? 29 : lane - 1;
    int lm2 = (lane < 2) ? lane + 28 : lane - 2;
    int lp1 = (lane >= 29) ? lane - 29 : lane + 1;
    int lp2 = (lane >= 28) ? lane - 28 : lane + 2;
    const unsigned FULL = 0xffffffffu;

    // b row (uniform across lanes)
    float brow[NM];
    const float* bp = b + (size_t)row * NM;
#pragma unroll
    for (int m = 0; m < NM; m++) brow[m] = bp[m];

    // State registers
    float x[10], eta[10], tau[10], bA[10];
#pragma unroll
    for (int i = 0; i < 10; i++) {
        x[i] = 1.f; eta[i] = 0.f; tau[i] = 0.f;
        float acc = 0.f;
#pragma unroll
        for (int m = 0; m < NM; m++)
            acc = fmaf(brow[m], A_s[m * PSTR + base + i], acc);
        bA[i] = acc;
    }

#pragma unroll 1
    for (int L = 0; L < NL; L++) {
        float g   = gamma_tv[L];
        float lam = lambda_tv[L];
        float al  = alpha[L];
        float ig  = 1.f / g;
        float ial = 1.f / al;
        float thr = lam * ig;

        float taps[KT + 1];
#pragma unroll
        for (int k = 0; k <= KT; k++) taps[k] = d_taps[L][k];

        const float* Vl = V_s + L * NM * PSTR;

        // --- residual r into rw[12..21]; pre-apply dual decrements ---
        float rw[34];
        float xm1 = __shfl_sync(FULL, x[9], lm1);
#pragma unroll
        for (int i = 0; i < 10; i++) {
            float xm = (i == 0) ? xm1 : x[i - 1];
            float dx = xm - x[i];
            float v  = fmaf(eta[i], ig, dx);
            float ua = fmaxf(fabsf(v) - thr, 0.f);
            float u  = copysignf(ua, v);
            float w  = fmaxf(fmaf(tau[i], ial, x[i]), 0.f);
            rw[12 + i] = bA[i] + al * w - tau[i] + g * u - eta[i];
            eta[i] -= g * u;
            tau[i] -= al * w;
        }

        // --- halo gather via shuffles (wrap mod 30 lanes) ---
#pragma unroll
        for (int e = 0; e < 10; e++) rw[2 + e]  = __shfl_sync(FULL, rw[12 + e], lm1);
        rw[0] = __shfl_sync(FULL, rw[20], lm2);
        rw[1] = __shfl_sync(FULL, rw[21], lm2);
#pragma unroll
        for (int e = 0; e < 10; e++) rw[22 + e] = __shfl_sync(FULL, rw[12 + e], lp1);
        rw[32] = __shfl_sync(FULL, rw[12], lp2);
        rw[33] = __shfl_sync(FULL, rw[13], lp2);

        // --- z = M^-1 r, truncated symmetric conv (registers only) ---
#pragma unroll
        for (int i = 0; i < 10; i++) {
            float acc = taps[0] * rw[12 + i];
#pragma unroll
            for (int k = 1; k <= KT; k++)
                acc = fmaf(taps[k], rw[12 + i + k] + rw[12 + i - k], acc);
            x[i] = acc;                        // z overwrites x
        }

        // --- c = A z (partial per lane, then butterfly) ---
        float cp[NM];
#pragma unroll
        for (int m = 0; m < NM; m++) cp[m] = 0.f;
#pragma unroll
        for (int i = 0; i < 10; i++) {
            float zi = x[i];
#pragma unroll
            for (int m = 0; m < NM; m++)
                cp[m] = fmaf(A_s[m * PSTR + base + i], zi, cp[m]);
        }
        if (lane >= 30) {
#pragma unroll
            for (int m = 0; m < NM; m++) cp[m] = 0.f;
        }
#pragma unroll
        for (int m = 0; m < NM; m++) {
#pragma unroll
            for (int o = 16; o > 0; o >>= 1)
                cp[m] += __shfl_xor_sync(FULL, cp[m], o);
        }

        // --- x = z - V c ---
#pragma unroll
        for (int i = 0; i < 10; i++) {
            float s = x[i];
#pragma unroll
            for (int m = 0; m < NM; m++)
                s = fmaf(-Vl[m * PSTR + base + i], cp[m], s);
            x[i] = s;
        }

        // --- dual increments with new x ---
        float xm1n = __shfl_sync(FULL, x[9], lm1);
#pragma unroll
        for (int i = 0; i < 10; i++) {
            float xm = (i == 0) ? xm1n : x[i - 1];
            eta[i] = fmaf(g, xm - x[i], eta[i]);
            tau[i] = fmaf(al, x[i], tau[i]);
        }
    }

    // --- write result ---
    if (lane < 30) {
        float* op = out + (size_t)row * NSPEC + lane * 10;
#pragma unroll
        for (int i = 0; i < 10; i++) op[i] = x[i];
    }
}

// ---------------------------------------------------------------------------
extern "C" void kernel_launch(void* const* d_in, const int* in_sizes, int n_in,
                              void* d_out, int out_size) {
    const float* b      = (const float*)d_in[0];
    const float* A      = (const float*)d_in[2];
    const float* gamma  = (const float*)d_in[3];
    const float* lam    = (const float*)d_in[4];
    const float* alpha  = (const float*)d_in[5];
    float* out = (float*)d_out;

    int rows = in_sizes[0] / NM;               // 131072

    size_t pre_smem  = PRE_SMEM_FLOATS * sizeof(float);
    size_t main_smem = MAIN_SMEM_FLOATS * sizeof(float);
    cudaFuncSetAttribute(precompute_kernel,
                         cudaFuncAttributeMaxDynamicSharedMemorySize, (int)pre_smem);
    cudaFuncSetAttribute(ladmm_kernel,
                         cudaFuncAttributeMaxDynamicSharedMemorySize, (int)main_smem);

    precompute_kernel<<<1, 512, pre_smem>>>(A, gamma, alpha);
    ladmm_kernel<<<rows / RPB, THREADS, main_smem>>>(b, A, gamma, lam, alpha, out);
}

// round 3
// speedup vs baseline: 1.7227x; 1.0647x over previous
#include <cuda_runtime.h>
#include <cuda_bf16.h>

#define NSPEC 300
#define NM    9
#define NL    5
#define KTAPS 16            // taps computed in precompute
#define KT    10            // taps used in main conv
#define RPB   8             // rows (=warps) per block
#define THREADS (RPB * 32)
#define LSTR  12            // floats per lane-run (16B aligned, conflict-free f4)
#define PSTR  (30 * LSTR)   // 360 floats per matrix row

typedef unsigned long long u64;

__device__ __forceinline__ u64 pk(float lo, float hi) {
    u64 r; asm("mov.b64 %0,{%1,%2};" : "=l"(r) : "f"(lo), "f"(hi)); return r;
}
__device__ __forceinline__ void upk(float& lo, float& hi, u64 v) {
    asm("mov.b64 {%0,%1},%2;" : "=f"(lo), "=f"(hi) : "l"(v));
}
__device__ __forceinline__ u64 fma2(u64 a, u64 b, u64 c) {
    u64 d; asm("fma.rn.f32x2 %0,%1,%2,%3;" : "=l"(d) : "l"(a), "l"(b), "l"(c)); return d;
}

// Precomputed per-layer factors
__device__ float d_taps[NL][KTAPS + 1];
__device__ float d_W[NL][NSPEC * NM];      // W[j*9+m] = (M^-1 A^T)[j][m]
__device__ float d_S[NL][NM * NM];
__device__ float d_Sinv[NL][NM * NM];
__device__ float d_V[NL][NM * NSPEC];      // V = W * Sinv, stored [m][j]

// ---------------------------------------------------------------------------
// Precompute kernel (1 block)
// ---------------------------------------------------------------------------
#define PRE_SMEM_FLOATS (5 * NSPEC * 2 + 8 + 50 * NSPEC)

__global__ void precompute_kernel(const float* __restrict__ A,
                                  const float* __restrict__ gamma_tv,
                                  const float* __restrict__ alpha) {
    extern __shared__ float psm[];
    float* im    = psm;
    float* qv    = im + NL * NSPEC;
    float* denom = qv + NL * NSPEC;
    float* ys    = denom + 8;

    int t = threadIdx.x;

    if (t < NL) {
        float g  = gamma_tv[t];
        float al = alpha[t];
        float D0 = al + 2.f * g;
        float off = -g;
        float b0v = 2.f * D0;
        float bnv = D0 + (g * g) / D0;
        float* imL = im + t * NSPEC;
        float* qL  = qv + t * NSPEC;
        float prev_cp = 0.f, prev_q = 0.f;
        for (int i = 0; i < NSPEC; i++) {
            float di = (i == 0) ? b0v : ((i == NSPEC - 1) ? bnv : D0);
            float m  = di - off * prev_cp;
            float imi = 1.f / m;
            imL[i] = imi;
            float ui = (i == 0) ? -D0 : ((i == NSPEC - 1) ? -g : 0.f);
            float qi = (ui - off * prev_q) * imi;
            qL[i] = qi;
            prev_cp = off * imi;
            prev_q  = qi;
        }
        for (int i = NSPEC - 2; i >= 0; i--)
            qL[i] -= off * imL[i] * qL[i + 1];
        float cg = g / D0;
        denom[t] = 1.f / (1.f + qL[0] + cg * qL[NSPEC - 1]);
    }
    __syncthreads();

    if (t < NL * 10) {
        int L = t / 10, rhs = t % 10;
        float g  = gamma_tv[L];
        float al = alpha[L];
        float D0 = al + 2.f * g;
        float off = -g;
        float* imL = im + L * NSPEC;
        float* y   = ys + t * NSPEC;
        const float* Arow = (rhs > 0) ? (A + (rhs - 1) * NSPEC) : nullptr;
        float prev = 0.f;
        for (int i = 0; i < NSPEC; i++) {
            float ri = (rhs == 0) ? ((i == 0) ? 1.f : 0.f) : Arow[i];
            float yi = (ri - off * prev) * imL[i];
            y[i] = yi;
            prev = yi;
        }
        for (int i = NSPEC - 2; i >= 0; i--)
            y[i] -= off * imL[i] * y[i + 1];
        float cg = g / D0;
        float fact = (y[0] + cg * y[NSPEC - 1]) * denom[L];
        if (rhs == 0) {
            for (int k = 0; k <= KTAPS; k++)
                d_taps[L][k] = y[k] - fact * qv[L * NSPEC + k];
        } else {
            int m = rhs - 1;
            for (int j = 0; j < NSPEC; j++)
                d_W[L][j * NM + m] = y[j] - fact * qv[L * NSPEC + j];
        }
    }
    __syncthreads();

    for (int idx = t; idx < NL * NM * NM; idx += blockDim.x) {
        int L = idx / (NM * NM);
        int pq = idx % (NM * NM);
        int p = pq / NM, q2 = pq % NM;
        float s = (p == q2) ? 1.f : 0.f;
        const float* Ap = A + p * NSPEC;
        for (int j = 0; j < NSPEC; j++)
            s = fmaf(Ap[j], d_W[L][j * NM + q2], s);
        d_S[L][pq] = s;
    }
    __syncthreads();

    if (t < NL) {
        float Mi[NM][2 * NM];
        for (int i = 0; i < NM; i++)
            for (int j = 0; j < NM; j++) {
                Mi[i][j] = d_S[t][i * NM + j];
                Mi[i][NM + j] = (i == j) ? 1.f : 0.f;
            }
        for (int col = 0; col < NM; col++) {
            int piv = col;
            float best = fabsf(Mi[col][col]);
            for (int r = col + 1; r < NM; r++) {
                float v = fabsf(Mi[r][col]);
                if (v > best) { best = v; piv = r; }
            }
            if (piv != col)
                for (int j = 0; j < 2 * NM; j++) {
                    float tmp = Mi[col][j]; Mi[col][j] = Mi[piv][j]; Mi[piv][j] = tmp;
                }
            float ip = 1.f / Mi[col][col];
            for (int j = 0; j < 2 * NM; j++) Mi[col][j] *= ip;
            for (int r = 0; r < NM; r++) {
                if (r == col) continue;
                float f = Mi[r][col];
                for (int j = 0; j < 2 * NM; j++) Mi[r][j] -= f * Mi[col][j];
            }
        }
        for (int i = 0; i < NM; i++)
            for (int j = 0; j < NM; j++)
                d_Sinv[t][i * NM + j] = Mi[i][NM + j];
    }
    __syncthreads();

    // V = W * Sinv, stored [L][m][j]
    for (int idx = t; idx < NL * NM * NSPEC; idx += blockDim.x) {
        int L = idx / (NM * NSPEC);
        int mj = idx % (NM * NSPEC);
        int m = mj / NSPEC, j = mj % NSPEC;
        float s = 0.f;
        for (int q = 0; q < NM; q++)
            s = fmaf(d_W[L][j * NM + q], d_Sinv[L][q * NM + m], s);
        d_V[L][m * NSPEC + j] = s;
    }
}

// ---------------------------------------------------------------------------
// Main kernel
// ---------------------------------------------------------------------------
#define MAIN_SMEM_FLOATS (NM * PSTR + NL * NM * PSTR)

__global__ void __launch_bounds__(THREADS, 2)
ladmm_kernel(const float* __restrict__ b,
             const float* __restrict__ A,
             const float* __restrict__ gamma_tv,
             const float* __restrict__ lambda_tv,
             const float* __restrict__ alpha,
             float* __restrict__ out) {
    extern __shared__ float sm[];
    float* A_s = sm;                          // [9][360]
    float* V_s = A_s + NM * PSTR;             // [45][360]

    int tid  = threadIdx.x;
    int warp = tid >> 5;
    int lane = tid & 31;
    int row  = blockIdx.x * RPB + warp;

    for (int idx = tid; idx < NM * NSPEC; idx += THREADS) {
        int m = idx / NSPEC, j = idx % NSPEC;
        A_s[m * PSTR + (j / 10) * LSTR + (j % 10)] = A[idx];
    }
    for (int idx = tid; idx < NL * NM * NSPEC; idx += THREADS) {
        int r = idx / NSPEC, j = idx % NSPEC;
        V_s[r * PSTR + (j / 10) * LSTR + (j % 10)] = (&d_V[0][0])[idx];
    }
    __syncthreads();

    int ml   = (lane < 30) ? lane : 29;
    int base = ml * LSTR;
    int lm1  = (lane == 0) ? 29 : lane - 1;
    int lp1  = (lane >= 29) ? lane - 29 : lane + 1;
    const unsigned FULL = 0xffffffffu;

    float brow[NM];
    const float* bp = b + (size_t)row * NM;
#pragma unroll
    for (int m = 0; m < NM; m++) brow[m] = bp[m];

    float x[10], eta[10], tau[10], bA[10];
#pragma unroll
    for (int i = 0; i < 10; i++) {
        x[i] = 1.f; eta[i] = 0.f; tau[i] = 0.f;
        float acc = 0.f;
#pragma unroll
        for (int m = 0; m < NM; m++)
            acc = fmaf(brow[m], A_s[m * PSTR + base + i], acc);
        bA[i] = acc;
    }

#pragma unroll 1
    for (int L = 0; L < NL; L++) {
        float g   = gamma_tv[L];
        float lam = lambda_tv[L];
        float al  = alpha[L];
        float ig  = 1.f / g;
        float ial = 1.f / al;
        float thr = lam * ig;

        float taps[KT + 1];
#pragma unroll
        for (int k = 0; k <= KT; k++) taps[k] = d_taps[L][k];

        const float* Vl = V_s + L * NM * PSTR;

        // --- elementwise with folded dual decrements ---
        float rw[30];
        float xm1 = __shfl_sync(FULL, x[9], lm1);
#pragma unroll
        for (int i = 0; i < 10; i++) {
            float xm = (i == 0) ? xm1 : x[i - 1];
            float dx = xm - x[i];
            float v  = fmaf(eta[i], ig, dx);
            float ua = fmaxf(fabsf(v) - thr, 0.f);
            float u  = copysignf(ua, v);
            eta[i] = fmaf(-g, u, eta[i]);
            float w  = fmaxf(fmaf(tau[i], ial, x[i]), 0.f);
            tau[i] = fmaf(-al, w, tau[i]);
            rw[10 + i] = bA[i] - tau[i] - eta[i];
        }

        // --- halo gather (+-10) ---
#pragma unroll
        for (int e = 0; e < 10; e++) rw[e]      = __shfl_sync(FULL, rw[10 + e], lm1);
#pragma unroll
        for (int e = 0; e < 10; e++) rw[20 + e] = __shfl_sync(FULL, rw[10 + e], lp1);

        // --- z = M^-1 r ---
#pragma unroll
        for (int i = 0; i < 10; i++) {
            float acc = taps[0] * rw[10 + i];
#pragma unroll
            for (int k = 1; k <= KT; k++)
                acc = fmaf(taps[k], rw[10 + i + k] + rw[10 + i - k], acc);
            x[i] = acc;
        }

        u64 z2[5];
#pragma unroll
        for (int p = 0; p < 5; p++) z2[p] = pk(x[2 * p], x[2 * p + 1]);

        // --- c = A z ---
        float cp[NM];
#pragma unroll
        for (int m = 0; m < NM; m++) {
            const float* ap = A_s + m * PSTR + base;
            float4 a0 = *reinterpret_cast<const float4*>(ap);
            float4 a1 = *reinterpret_cast<const float4*>(ap + 4);
            float2 a2 = *reinterpret_cast<const float2*>(ap + 8);
            u64 acc = fma2(pk(a0.x, a0.y), z2[0],
                      fma2(pk(a0.z, a0.w), z2[1],
                      fma2(pk(a1.x, a1.y), z2[2],
                      fma2(pk(a1.z, a1.w), z2[3],
                      fma2(pk(a2.x, a2.y), z2[4], 0ULL)))));
            float lo, hi; upk(lo, hi, acc);
            cp[m] = lo + hi;
        }
        if (lane >= 30) {
#pragma unroll
            for (int m = 0; m < NM; m++) cp[m] = 0.f;
        }
#pragma unroll
        for (int m = 0; m < NM; m++) {
#pragma unroll
            for (int o = 16; o > 0; o >>= 1)
                cp[m] += __shfl_xor_sync(FULL, cp[m], o);
        }

        // --- x = z - V c ---
#pragma unroll
        for (int m = 0; m < NM; m++) {
            u64 cm2 = pk(-cp[m], -cp[m]);
            const float* vp = Vl + m * PSTR + base;
            float4 v0 = *reinterpret_cast<const float4*>(vp);
            float4 v1 = *reinterpret_cast<const float4*>(vp + 4);
            float2 v2 = *reinterpret_cast<const float2*>(vp + 8);
            z2[0] = fma2(pk(v0.x, v0.y), cm2, z2[0]);
            z2[1] = fma2(pk(v0.z, v0.w), cm2, z2[1]);
            z2[2] = fma2(pk(v1.x, v1.y), cm2, z2[2]);
            z2[3] = fma2(pk(v1.z, v1.w), cm2, z2[3]);
            z2[4] = fma2(pk(v2.x, v2.y), cm2, z2[4]);
        }
#pragma unroll
        for (int p = 0; p < 5; p++) upk(x[2 * p], x[2 * p + 1], z2[p]);

        // --- dual increments ---
        float xm1n = __shfl_sync(FULL, x[9], lm1);
#pragma unroll
        for (int i = 0; i < 10; i++) {
            float xm = (i == 0) ? xm1n : x[i - 1];
            eta[i] = fmaf(g, xm - x[i], eta[i]);
            tau[i] = fmaf(al, x[i], tau[i]);
        }
    }

    if (lane < 30) {
        float* op = out + (size_t)row * NSPEC + lane * 10;
#pragma unroll
        for (int i = 0; i < 10; i++) op[i] = x[i];
    }
}

// ---------------------------------------------------------------------------
extern "C" void kernel_launch(void* const* d_in, const int* in_sizes, int n_in,
                              void* d_out, int out_size) {
    const float* b      = (const float*)d_in[0];
    const float* A      = (const float*)d_in[2];
    const float* gamma  = (const float*)d_in[3];
    const float* lam    = (const float*)d_in[4];
    const float* alpha  = (const float*)d_in[5];
    float* out = (float*)d_out;

    int rows = in_sizes[0] / NM;               // 131072

    size_t pre_smem  = PRE_SMEM_FLOATS * sizeof(float);
    size_t main_smem = MAIN_SMEM_FLOATS * sizeof(float);
    cudaFuncSetAttribute(precompute_kernel,
                         cudaFuncAttributeMaxDynamicSharedMemorySize, (int)pre_smem);
    cudaFuncSetAttribute(ladmm_kernel,
                         cudaFuncAttributeMaxDynamicSharedMemorySize, (int)main_smem);

    precompute_kernel<<<1, 512, pre_smem>>>(A, gamma, alpha);
    ladmm_kernel<<<rows / RPB, THREADS, main_smem>>>(b, A, gamma, lam, alpha, out);
}

// round 5
// speedup vs baseline: 2.4930x; 1.4472x over previous
#include <cuda_runtime.h>
#include <cuda_bf16.h>

#define NSPEC 300
#define NM    9
#define NL    5
#define KTAPS 16            // taps computed in precompute
#define KT    9             // taps used in main conv
#define RPB   8             // warps per block
#define ROWS_PER_WARP 2
#define THREADS (RPB * 32)
#define LSTR  13            // floats per lane-run: odd -> scalar LDS conflict-free
#define PSTR  (30 * LSTR)   // 390 floats per matrix row

typedef unsigned long long u64;

__device__ __forceinline__ u64 pk(float lo, float hi) {
    u64 r; asm("mov.b64 %0,{%1,%2};" : "=l"(r) : "f"(lo), "f"(hi)); return r;
}
__device__ __forceinline__ void upk(float& lo, float& hi, u64 v) {
    asm("mov.b64 {%0,%1},%2;" : "=f"(lo), "=f"(hi) : "l"(v));
}
__device__ __forceinline__ u64 fma2(u64 a, u64 b, u64 c) {
    u64 d; asm("fma.rn.f32x2 %0,%1,%2,%3;" : "=l"(d) : "l"(a), "l"(b), "l"(c)); return d;
}
__device__ __forceinline__ u64 add2(u64 a, u64 b) {
    u64 d; asm("add.rn.f32x2 %0,%1,%2;" : "=l"(d) : "l"(a), "l"(b)); return d;
}

// Precomputed per-layer factors
__device__ float d_taps[NL][KTAPS + 1];
__device__ float d_W[NL][NSPEC * NM];
__device__ float d_S[NL][NM * NM];
__device__ float d_Sinv[NL][NM * NM];
__device__ float d_V[NL][NM * NSPEC];      // NEGATED V = -(W * Sinv), stored [m][j]

// ---------------------------------------------------------------------------
// Precompute kernel (1 block)
// ---------------------------------------------------------------------------
#define PRE_SMEM_FLOATS (5 * NSPEC * 2 + 8 + 50 * NSPEC)

__global__ void precompute_kernel(const float* __restrict__ A,
                                  const float* __restrict__ gamma_tv,
                                  const float* __restrict__ alpha) {
    extern __shared__ float psm[];
    float* im    = psm;
    float* qv    = im + NL * NSPEC;
    float* denom = qv + NL * NSPEC;
    float* ys    = denom + 8;

    int t = threadIdx.x;

    if (t < NL) {
        float g  = gamma_tv[t];
        float al = alpha[t];
        float D0 = al + 2.f * g;
        float off = -g;
        float b0v = 2.f * D0;
        float bnv = D0 + (g * g) / D0;
        float* imL = im + t * NSPEC;
        float* qL  = qv + t * NSPEC;
        float prev_cp = 0.f, prev_q = 0.f;
        for (int i = 0; i < NSPEC; i++) {
            float di = (i == 0) ? b0v : ((i == NSPEC - 1) ? bnv : D0);
            float m  = di - off * prev_cp;
            float imi = 1.f / m;
            imL[i] = imi;
            float ui = (i == 0) ? -D0 : ((i == NSPEC - 1) ? -g : 0.f);
            float qi = (ui - off * prev_q) * imi;
            qL[i] = qi;
            prev_cp = off * imi;
            prev_q  = qi;
        }
        for (int i = NSPEC - 2; i >= 0; i--)
            qL[i] -= off * imL[i] * qL[i + 1];
        float cg = g / D0;
        denom[t] = 1.f / (1.f + qL[0] + cg * qL[NSPEC - 1]);
    }
    __syncthreads();

    if (t < NL * 10) {
        int L = t / 10, rhs = t % 10;
        float g  = gamma_tv[L];
        float al = alpha[L];
        float D0 = al + 2.f * g;
        float off = -g;
        float* imL = im + L * NSPEC;
        float* y   = ys + t * NSPEC;
        const float* Arow = (rhs > 0) ? (A + (rhs - 1) * NSPEC) : nullptr;
        float prev = 0.f;
        for (int i = 0; i < NSPEC; i++) {
            float ri = (rhs == 0) ? ((i == 0) ? 1.f : 0.f) : Arow[i];
            float yi = (ri - off * prev) * imL[i];
            y[i] = yi;
            prev = yi;
        }
        for (int i = NSPEC - 2; i >= 0; i--)
            y[i] -= off * imL[i] * y[i + 1];
        float cg = g / D0;
        float fact = (y[0] + cg * y[NSPEC - 1]) * denom[L];
        if (rhs == 0) {
            for (int k = 0; k <= KTAPS; k++)
                d_taps[L][k] = y[k] - fact * qv[L * NSPEC + k];
        } else {
            int m = rhs - 1;
            for (int j = 0; j < NSPEC; j++)
                d_W[L][j * NM + m] = y[j] - fact * qv[L * NSPEC + j];
        }
    }
    __syncthreads();

    for (int idx = t; idx < NL * NM * NM; idx += blockDim.x) {
        int L = idx / (NM * NM);
        int pq = idx % (NM * NM);
        int p = pq / NM, q2 = pq % NM;
        float s = (p == q2) ? 1.f : 0.f;
        const float* Ap = A + p * NSPEC;
        for (int j = 0; j < NSPEC; j++)
            s = fmaf(Ap[j], d_W[L][j * NM + q2], s);
        d_S[L][pq] = s;
    }
    __syncthreads();

    if (t < NL) {
        float Mi[NM][2 * NM];
        for (int i = 0; i < NM; i++)
            for (int j = 0; j < NM; j++) {
                Mi[i][j] = d_S[t][i * NM + j];
                Mi[i][NM + j] = (i == j) ? 1.f : 0.f;
            }
        for (int col = 0; col < NM; col++) {
            int piv = col;
            float best = fabsf(Mi[col][col]);
            for (int r = col + 1; r < NM; r++) {
                float v = fabsf(Mi[r][col]);
                if (v > best) { best = v; piv = r; }
            }
            if (piv != col)
                for (int j = 0; j < 2 * NM; j++) {
                    float tmp = Mi[col][j]; Mi[col][j] = Mi[piv][j]; Mi[piv][j] = tmp;
                }
            float ip = 1.f / Mi[col][col];
            for (int j = 0; j < 2 * NM; j++) Mi[col][j] *= ip;
            for (int r = 0; r < NM; r++) {
                if (r == col) continue;
                float f = Mi[r][col];
                for (int j = 0; j < 2 * NM; j++) Mi[r][j] -= f * Mi[col][j];
            }
        }
        for (int i = 0; i < NM; i++)
            for (int j = 0; j < NM; j++)
                d_Sinv[t][i * NM + j] = Mi[i][NM + j];
    }
    __syncthreads();

    // d_V = -(W * Sinv), stored [L][m][j]  (negated so main kernel uses pure FMA)
    for (int idx = t; idx < NL * NM * NSPEC; idx += blockDim.x) {
        int L = idx / (NM * NSPEC);
        int mj = idx % (NM * NSPEC);
        int m = mj / NSPEC, j = mj % NSPEC;
        float s = 0.f;
        for (int q = 0; q < NM; q++)
            s = fmaf(d_W[L][j * NM + q], d_Sinv[L][q * NM + m], s);
        d_V[L][m * NSPEC + j] = -s;
    }
}

// ---------------------------------------------------------------------------
// Main kernel: one warp handles TWO rows; 30 lanes x 10 elements per row.
// Scalar LDS (stride 13 -> conflict-free) shared between both rows' FMAs.
// Conv runs packed f32x2 (rowA,rowB per register).
// ---------------------------------------------------------------------------
#define MAIN_SMEM_FLOATS ((NM + NL * NM) * PSTR)

__global__ void __launch_bounds__(THREADS, 2)
ladmm_kernel(const float* __restrict__ b,
             const float* __restrict__ A,
             const float* __restrict__ gamma_tv,
             const float* __restrict__ lambda_tv,
             const float* __restrict__ alpha,
             float* __restrict__ out) {
    extern __shared__ float sm[];
    float* A_s = sm;                          // [9][390]
    float* V_s = A_s + NM * PSTR;             // [45][390] (negated V)

    int tid  = threadIdx.x;
    int warp = tid >> 5;
    int lane = tid & 31;
    int rowA = (blockIdx.x * RPB + warp) * ROWS_PER_WARP;
    int rowB = rowA + 1;

    for (int idx = tid; idx < NM * NSPEC; idx += THREADS) {
        int m = idx / NSPEC, j = idx % NSPEC;
        A_s[m * PSTR + (j / 10) * LSTR + (j % 10)] = A[idx];
    }
    for (int idx = tid; idx < NL * NM * NSPEC; idx += THREADS) {
        int r = idx / NSPEC, j = idx % NSPEC;
        V_s[r * PSTR + (j / 10) * LSTR + (j % 10)] = (&d_V[0][0])[idx];
    }
    __syncthreads();

    int ml   = (lane < 30) ? lane : 29;
    int base = ml * LSTR;
    int lm1  = (lane == 0) ? 29 : lane - 1;
    int lp1  = (lane >= 29) ? lane - 29 : lane + 1;
    const unsigned FULL = 0xffffffffu;

    // State (scalar, per row)
    float xA[10], xB[10], eA[10], eB[10], tA[10], tB[10], bAA[10], bAB[10];
    {
        float browA[NM], browB[NM];
        const float* bpA = b + (size_t)rowA * NM;
        const float* bpB = b + (size_t)rowB * NM;
#pragma unroll
        for (int m = 0; m < NM; m++) { browA[m] = bpA[m]; browB[m] = bpB[m]; }
#pragma unroll
        for (int i = 0; i < 10; i++) {
            xA[i] = 1.f; xB[i] = 1.f;
            eA[i] = 0.f; eB[i] = 0.f;
            tA[i] = 0.f; tB[i] = 0.f;
            bAA[i] = 0.f; bAB[i] = 0.f;
        }
#pragma unroll
        for (int m = 0; m < NM; m++) {
            const float* ap = A_s + m * PSTR + base;
#pragma unroll
            for (int i = 0; i < 10; i++) {
                float a = ap[i];
                bAA[i] = fmaf(browA[m], a, bAA[i]);
                bAB[i] = fmaf(browB[m], a, bAB[i]);
            }
        }
    }

#pragma unroll 1
    for (int L = 0; L < NL; L++) {
        float g   = gamma_tv[L];
        float lam = lambda_tv[L];
        float al  = alpha[L];
        float ig  = 1.f / g;
        float ial = 1.f / al;
        float thr = lam * ig;

        const float* Vl = V_s + L * NM * PSTR;

        // --- elementwise (scalar, both rows), residual packed into rw2 ---
        u64 rw2[10];
        float xm1A = __shfl_sync(FULL, xA[9], lm1);
        float xm1B = __shfl_sync(FULL, xB[9], lm1);
#pragma unroll
        for (int i = 0; i < 10; i++) {
            float xmA = (i == 0) ? xm1A : xA[i - 1];
            float vA  = fmaf(eA[i], ig, xmA - xA[i]);
            float uA  = copysignf(fmaxf(fabsf(vA) - thr, 0.f), vA);
            eA[i] = fmaf(-g, uA, eA[i]);
            float wA  = fmaxf(fmaf(tA[i], ial, xA[i]), 0.f);
            tA[i] = fmaf(-al, wA, tA[i]);
            float rA  = bAA[i] - tA[i] - eA[i];

            float xmB = (i == 0) ? xm1B : xB[i - 1];
            float vB  = fmaf(eB[i], ig, xmB - xB[i]);
            float uB  = copysignf(fmaxf(fabsf(vB) - thr, 0.f), vB);
            eB[i] = fmaf(-g, uB, eB[i]);
            float wB  = fmaxf(fmaf(tB[i], ial, xB[i]), 0.f);
            tB[i] = fmaf(-al, wB, tB[i]);
            float rB  = bAB[i] - tB[i] - eB[i];

            rw2[i] = pk(rA, rB);
        }

        // --- packed taps ---
        u64 tap2[KT + 1];
#pragma unroll
        for (int k = 0; k <= KT; k++) {
            float tk = d_taps[L][k];
            tap2[k] = pk(tk, tk);
        }

        // --- z = M^-1 r : packed conv, streaming halo ---
        u64 acc2[10];
#pragma unroll
        for (int i = 0; i < 10; i++) {
            u64 acc = fma2(tap2[i], rw2[0], 0ULL);
#pragma unroll
            for (int j = 1; j < 10; j++) {
                int k = (i > j) ? (i - j) : (j - i);
                acc = fma2(tap2[k], rw2[j], acc);
            }
            acc2[i] = acc;
        }
        // left halo: neighbor lm1's elements e=1..9 at positions e-10
#pragma unroll
        for (int e = 1; e < 10; e++) {
            u64 v = __shfl_sync(FULL, rw2[e], lm1);
#pragma unroll
            for (int i = 0; i < e; i++)
                acc2[i] = fma2(tap2[10 + i - e], v, acc2[i]);
        }
        // right halo: neighbor lp1's elements e=0..8 at positions 10+e
#pragma unroll
        for (int e = 0; e < 9; e++) {
            u64 v = __shfl_sync(FULL, rw2[e], lp1);
#pragma unroll
            for (int i = e + 1; i < 10; i++)
                acc2[i] = fma2(tap2[10 + e - i], v, acc2[i]);
        }
#pragma unroll
        for (int i = 0; i < 10; i++) upk(xA[i], xB[i], acc2[i]);   // z -> x

        // --- c = A z : shared scalar LDS feeds both rows ---
        float cpA[NM], cpB[NM];
#pragma unroll
        for (int m = 0; m < NM; m++) {
            const float* ap = A_s + m * PSTR + base;
            float sa = 0.f, sb = 0.f;
#pragma unroll
            for (int i = 0; i < 10; i++) {
                float a = ap[i];
                sa = fmaf(a, xA[i], sa);
                sb = fmaf(a, xB[i], sb);
            }
            cpA[m] = sa; cpB[m] = sb;
        }
        u64 cp2[NM];
#pragma unroll
        for (int m = 0; m < NM; m++)
            cp2[m] = (lane < 30) ? pk(cpA[m], cpB[m]) : 0ULL;
#pragma unroll
        for (int m = 0; m < NM; m++) {
#pragma unroll
            for (int o = 16; o > 0; o >>= 1)
                cp2[m] = add2(cp2[m], __shfl_xor_sync(FULL, cp2[m], o));
        }
#pragma unroll
        for (int m = 0; m < NM; m++) upk(cpA[m], cpB[m], cp2[m]);

        // --- x = z + Vneg * c : shared scalar LDS feeds both rows ---
#pragma unroll
        for (int m = 0; m < NM; m++) {
            const float* vp = Vl + m * PSTR + base;
            float ca = cpA[m], cb = cpB[m];
#pragma unroll
            for (int i = 0; i < 10; i++) {
                float v = vp[i];
                xA[i] = fmaf(v, ca, xA[i]);
                xB[i] = fmaf(v, cb, xB[i]);
            }
        }

        // --- dual increments ---
        float xnA = __shfl_sync(FULL, xA[9], lm1);
        float xnB = __shfl_sync(FULL, xB[9], lm1);
#pragma unroll
        for (int i = 0; i < 10; i++) {
            float xmA = (i == 0) ? xnA : xA[i - 1];
            eA[i] = fmaf(g, xmA - xA[i], eA[i]);
            tA[i] = fmaf(al, xA[i], tA[i]);
            float xmB = (i == 0) ? xnB : xB[i - 1];
            eB[i] = fmaf(g, xmB - xB[i], eB[i]);
            tB[i] = fmaf(al, xB[i], tB[i]);
        }
    }

    if (lane < 30) {
        float* opA = out + (size_t)rowA * NSPEC + lane * 10;
        float* opB = out + (size_t)rowB * NSPEC + lane * 10;
#pragma unroll
        for (int i = 0; i < 10; i++) { opA[i] = xA[i]; opB[i] = xB[i]; }
    }
}

// ---------------------------------------------------------------------------
extern "C" void kernel_launch(void* const* d_in, const int* in_sizes, int n_in,
                              void* d_out, int out_size) {
    const float* b      = (const float*)d_in[0];
    const float* A      = (const float*)d_in[2];
    const float* gamma  = (const float*)d_in[3];
    const float* lam    = (const float*)d_in[4];
    const float* alpha  = (const float*)d_in[5];
    float* out = (float*)d_out;

    int rows = in_sizes[0] / NM;               // 131072

    size_t pre_smem  = PRE_SMEM_FLOATS * sizeof(float);
    size_t main_smem = MAIN_SMEM_FLOATS * sizeof(float);
    cudaFuncSetAttribute(precompute_kernel,
                         cudaFuncAttributeMaxDynamicSharedMemorySize, (int)pre_smem);
    cudaFuncSetAttribute(ladmm_kernel,
                         cudaFuncAttributeMaxDynamicSharedMemorySize, (int)main_smem);

    precompute_kernel<<<1, 512, pre_smem>>>(A, gamma, alpha);
    ladmm_kernel<<<rows / (RPB * ROWS_PER_WARP), THREADS, main_smem>>>(
        b, A, gamma, lam, alpha, out);
}